// round 16
// baseline (speedup 1.0000x reference)
#include <cuda_runtime.h>
#include <cuda_fp16.h>
#include <cstdint>

#define NN   8192
#define FIN  256
#define FOUT 128
#define L2E  1.44269504f
#define LRA  0.2f
#define CK   128                   // j per chunk (k_main)
#define JSPLIT 4
#define JBLK (NN / JSPLIT)         // 2048
#define NCH  (JBLK / CK)           // 16 chunks per block
#define NTI  (NN / 64)             // 128 B tiles (64j each)
#define TB64 16384                 // one 64j tile: 64j x 128d x 2B fp16
#define CHUNK_B 32768              // per-chunk B buffer: 2 x 64j tiles
#define XA_TERM 4194304            // bytes per A-term (8192x256 bf16)
#define TB_TERM 65536              // bytes per trans-term (256x128 bf16)
#define HB 49152                   // k_hgemm smem half-buffer stride

__device__ float g_e1s[NN];        // 1.4427 * e1
__device__ float g_e2s[NN];        // 1.4427 * e2
__device__ __align__(128) unsigned char g_xa[2 * XA_TERM];               // 8MB
__device__ __align__(128) unsigned char g_tb[2 * TB_TERM];               // 128KB
__device__ __align__(128) unsigned char g_bt[(size_t)NTI * TB64];        // 2MB
__device__ __align__(16)  float g_part[JSPLIT][NN * FOUT];               // 16MB
__device__ float g_psum[JSPLIT][NN];

// ------------------------- helpers -----------------------------------------
__device__ __forceinline__ uint32_t smem_u32(const void* p) {
    uint32_t a;
    asm("{ .reg .u64 t; cvta.to.shared.u64 t, %1; cvt.u32.u64 %0, t; }" : "=r"(a) : "l"(p));
    return a;
}
__device__ __forceinline__ uint32_t pack16(float lo, float hi) {   // fp16x2
    uint32_t r;
    asm("cvt.rn.f16x2.f32 %0, %1, %2;" : "=r"(r) : "f"(hi), "f"(lo));
    return r;
}
__device__ __forceinline__ uint32_t packbf(float lo, float hi) {   // bf16x2
    uint32_t r;
    asm("cvt.rn.bf16x2.f32 %0, %1, %2;" : "=r"(r) : "f"(hi), "f"(lo));
    return r;
}
__device__ __forceinline__ void splitbf(float a, float b, uint32_t& hi, uint32_t& lo) {
    hi = packbf(a, b);
    float ra = a - __uint_as_float(hi << 16);
    float rb = b - __uint_as_float(hi & 0xFFFF0000u);
    lo = packbf(ra, rb);
}
__device__ __forceinline__ uint32_t packmask(float lo, float hi, int ax, int ay) {
    uint32_t p = pack16(lo, hi);
    uint32_t m = (uint32_t)ax * 0x3C00u + (uint32_t)ay * 0x3C000000u;
    uint32_t r;
    asm("mul.f16x2 %0, %1, %2;" : "=r"(r) : "r"(p), "r"(m));
    return r;
}
__device__ __forceinline__ float pcalc(float se1, float se2) {
    float s = se1 + se2;
    s = fmaxf(s, LRA * s);
    float p;
    asm("ex2.approx.f32 %0, %1;" : "=f"(p) : "f"(s));
    return p;
}
__device__ __forceinline__ float ex2f(float s) {
    float p;
    asm("ex2.approx.f32 %0, %1;" : "=f"(p) : "f"(s));
    return p;
}
__device__ __forceinline__ void mma16816(float* c, const uint32_t* a, const uint32_t* b) {
    asm volatile("mma.sync.aligned.m16n8k16.row.col.f32.f16.f16.f32 "
        "{%0,%1,%2,%3}, {%4,%5,%6,%7}, {%8,%9}, {%0,%1,%2,%3};"
        : "+f"(c[0]), "+f"(c[1]), "+f"(c[2]), "+f"(c[3])
        : "r"(a[0]), "r"(a[1]), "r"(a[2]), "r"(a[3]), "r"(b[0]), "r"(b[1]));
}
__device__ __forceinline__ void mma_bf(float* c, const uint32_t* a, const uint32_t* b) {
    asm volatile("mma.sync.aligned.m16n8k16.row.col.f32.bf16.bf16.f32 "
        "{%0,%1,%2,%3}, {%4,%5,%6,%7}, {%8,%9}, {%0,%1,%2,%3};"
        : "+f"(c[0]), "+f"(c[1]), "+f"(c[2]), "+f"(c[3])
        : "r"(a[0]), "r"(a[1]), "r"(a[2]), "r"(a[3]), "r"(b[0]), "r"(b[1]));
}
#define LDMX4(r, a) \
    asm volatile("ldmatrix.sync.aligned.m8n8.x4.shared.b16 {%0,%1,%2,%3}, [%4];" \
        : "=r"((r)[0]), "=r"((r)[1]), "=r"((r)[2]), "=r"((r)[3]) : "r"(a))
#define CP_ASYNC(dst, src) \
    asm volatile("cp.async.cg.shared.global [%0], [%1], 16;" :: "r"(dst), "l"(src))
#define CP_COMMIT() asm volatile("cp.async.commit_group;" ::: "memory")
#define CP_WAIT1()  asm volatile("cp.async.wait_group 1;"  ::: "memory")

// ---------------------------------------------------------------------------
// Kernel 1 (cvt): x -> bf16 hi/lo A tiles; trans -> bf16 hi/lo B tiles.
// ---------------------------------------------------------------------------
__global__ __launch_bounds__(256) void k_cvt(const float* __restrict__ x,
                                             const float* __restrict__ trans)
{
    const int bx = blockIdx.x, t = threadIdx.x;
    if (bx < 512) {
        const int mt = bx;
        #pragma unroll
        for (int i = 0; i < 2; i++) {
            int rho = i * 256 + t;
            int ks = rho >> 5, blk = (rho >> 3) & 3, dr = rho & 7;
            int row = mt * 16 + (blk & 1) * 8 + dr;
            int kb  = ks * 16 + (blk >> 1) * 8;
            const float4* xp = (const float4*)(x + (size_t)row * FIN + kb);
            float4 v0 = __ldg(xp), v1 = __ldg(xp + 1);
            uint32_t hi4[4], lo4[4];
            splitbf(v0.x, v0.y, hi4[0], lo4[0]);
            splitbf(v0.z, v0.w, hi4[1], lo4[1]);
            splitbf(v1.x, v1.y, hi4[2], lo4[2]);
            splitbf(v1.z, v1.w, hi4[3], lo4[3]);
            uint32_t off = (uint32_t)(mt * 16 + ks) * 512 + blk * 128 + dr * 16;
            *(uint4*)(g_xa + off)           = make_uint4(hi4[0], hi4[1], hi4[2], hi4[3]);
            *(uint4*)(g_xa + XA_TERM + off) = make_uint4(lo4[0], lo4[1], lo4[2], lo4[3]);
        }
    } else {
        const int ks = bx - 512;
        int dp = t >> 5, blk = (t >> 3) & 3, dr = t & 7;
        int kk = blk & 1, dn = blk >> 1;
        int n  = dp * 16 + dn * 8 + dr;
        int kb = ks * 16 + kk * 8;
        uint32_t hi4[4], lo4[4];
        #pragma unroll
        for (int m = 0; m < 4; m++) {
            float a = __ldg(trans + (size_t)(kb + 2*m)     * FOUT + n);
            float b = __ldg(trans + (size_t)(kb + 2*m + 1) * FOUT + n);
            splitbf(a, b, hi4[m], lo4[m]);
        }
        uint32_t off = (uint32_t)(ks * 8 + dp) * 512 + blk * 128 + dr * 16;
        *(uint4*)(g_tb + off)           = make_uint4(hi4[0], hi4[1], hi4[2], hi4[3]);
        *(uint4*)(g_tb + TB_TERM + off) = make_uint4(lo4[0], lo4[1], lo4[2], lo4[3]);
    }
}

// ---------------------------------------------------------------------------
// Kernel 2 (hgemm): h = x@trans via 3-term bf16 HMMA (unchanged).
// ---------------------------------------------------------------------------
__global__ __launch_bounds__(256) void k_hgemm(const float* __restrict__ aw)
{
    extern __shared__ unsigned char smem[];
    const uint32_t sb = smem_u32(smem);
    const int t = threadIdx.x, w = t >> 5, l = t & 31;
    const int rg = w >> 1, cg = w & 1;
    const int g = l >> 2, qh = l & 3, q2 = qh * 2;
    const int bx = blockIdx.x;

    #pragma unroll
    for (int kc = 0; kc < 2; kc++) {
        const uint32_t bufb = sb + kc * HB;
        #pragma unroll
        for (int q = 0; q < 2; q++) {
            int idx = q * 256 + t;
            int mtl = idx >> 7, rem = idx & 127;
            const unsigned char* src = g_xa + (size_t)((bx*4 + mtl)*16 + kc*4) * 512 + rem*16;
            uint32_t dst = bufb + mtl * 2048 + rem * 16;
            CP_ASYNC(dst, src);
            CP_ASYNC(dst + 8192, src + XA_TERM);
        }
        #pragma unroll
        for (int q = 0; q < 4; q++) {
            int idx = q * 256 + t;
            const unsigned char* src = g_tb + kc * 16384 + idx * 16;
            uint32_t dst = bufb + 16384 + idx * 16;
            CP_ASYNC(dst, src);
            CP_ASYNC(dst + 16384, src + TB_TERM);
        }
        CP_COMMIT();
    }

    float c_[8][4];
    #pragma unroll
    for (int td = 0; td < 8; td++)
        #pragma unroll
        for (int k = 0; k < 4; k++) c_[td][k] = 0.f;

    for (int kc = 0; kc < 4; kc++) {
        CP_WAIT1();
        __syncthreads();
        const uint32_t bufb = sb + (kc & 1) * HB;
        #pragma unroll
        for (int ksl = 0; ksl < 4; ksl++) {
            uint32_t ahi[4], alo[4];
            const uint32_t aad = bufb + rg * 2048 + ksl * 512
                               + (l >> 3) * 128 + (l & 7) * 16;
            LDMX4(ahi, aad);
            LDMX4(alo, aad + 8192);
            #pragma unroll
            for (int dpl = 0; dpl < 4; dpl++) {
                const int dp = cg * 4 + dpl;
                uint32_t bhi[4], blo[4];
                const uint32_t bad = bufb + 16384 + (ksl * 8 + dp) * 512
                                   + (l >> 3) * 128 + (l & 7) * 16;
                LDMX4(bhi, bad);
                LDMX4(blo, bad + 16384);
                mma_bf(c_[2*dpl],     ahi, bhi);
                mma_bf(c_[2*dpl + 1], ahi, bhi + 2);
                mma_bf(c_[2*dpl],     alo, bhi);
                mma_bf(c_[2*dpl + 1], alo, bhi + 2);
                mma_bf(c_[2*dpl],     ahi, blo);
                mma_bf(c_[2*dpl + 1], ahi, blo + 2);
            }
        }
        __syncthreads();
        if (kc + 2 < 4) {
            const int kn = kc + 2;
            const uint32_t bufb2 = sb + (kc & 1) * HB;
            #pragma unroll
            for (int q = 0; q < 2; q++) {
                int idx = q * 256 + t;
                int mtl = idx >> 7, rem = idx & 127;
                const unsigned char* src = g_xa + (size_t)((bx*4 + mtl)*16 + kn*4) * 512 + rem*16;
                uint32_t dst = bufb2 + mtl * 2048 + rem * 16;
                CP_ASYNC(dst, src);
                CP_ASYNC(dst + 8192, src + XA_TERM);
            }
            #pragma unroll
            for (int q = 0; q < 4; q++) {
                int idx = q * 256 + t;
                const unsigned char* src = g_tb + kn * 16384 + idx * 16;
                uint32_t dst = bufb2 + 16384 + idx * 16;
                CP_ASYNC(dst, src);
                CP_ASYNC(dst + 16384, src + TB_TERM);
            }
        }
        CP_COMMIT();
    }

    // ---- epilogue: h tile to smem + e1/e2 partials ----
    __syncthreads();
    float* hs   = (float*)smem;              // 64 x 128 fp32 = 32KB
    float* ered = (float*)(smem + 32768);    // [64][2cg][2] floats
    const int r0 = rg * 16 + g, r1 = r0 + 8;
    float s1a = 0.f, s2a = 0.f, s1b = 0.f, s2b = 0.f;
    #pragma unroll
    for (int td = 0; td < 8; td++) {
        const int cb = cg * 64 + td * 8 + q2;
        hs[r0 * 128 + cb]     = c_[td][0];
        hs[r0 * 128 + cb + 1] = c_[td][1];
        hs[r1 * 128 + cb]     = c_[td][2];
        hs[r1 * 128 + cb + 1] = c_[td][3];
        const float w10 = __ldg(aw + cb), w11 = __ldg(aw + cb + 1);
        const float w20 = __ldg(aw + FOUT + cb), w21 = __ldg(aw + FOUT + cb + 1);
        s1a += c_[td][0] * w10 + c_[td][1] * w11;
        s2a += c_[td][0] * w20 + c_[td][1] * w21;
        s1b += c_[td][2] * w10 + c_[td][3] * w11;
        s2b += c_[td][2] * w20 + c_[td][3] * w21;
    }
    #pragma unroll
    for (int o = 1; o <= 2; o <<= 1) {
        s1a += __shfl_xor_sync(0xFFFFFFFFu, s1a, o);
        s2a += __shfl_xor_sync(0xFFFFFFFFu, s2a, o);
        s1b += __shfl_xor_sync(0xFFFFFFFFu, s1b, o);
        s2b += __shfl_xor_sync(0xFFFFFFFFu, s2b, o);
    }
    if (qh == 0) {
        ered[r0 * 4 + cg * 2]     = s1a;
        ered[r0 * 4 + cg * 2 + 1] = s2a;
        ered[r1 * 4 + cg * 2]     = s1b;
        ered[r1 * 4 + cg * 2 + 1] = s2b;
    }
    __syncthreads();

    // ---- build remapped fp16 B tile (k_prep logic, smem source) ----
    unsigned char* tb = g_bt + (size_t)bx * TB64;
    #pragma unroll
    for (int i = 0; i < 4; i++) {
        int rho = i * 256 + t;
        int blk = rho >> 3, dr = rho & 7;
        int kk = blk & 1, dn = (blk >> 1) & 1, dp8 = (blk >> 2) & 7, st = blk >> 5;
        int d  = dp8 * 16 + dn * 8 + dr;
        int jb = st * 16 + kk * 2;
        uint32_t h4[4];
        #pragma unroll
        for (int m = 0; m < 4; m++)
            h4[m] = pack16(hs[(jb + 4*m) * 128 + d], hs[(jb + 4*m + 1) * 128 + d]);
        *(uint4*)(tb + (uint32_t)blk * 128 + dr * 16) =
            make_uint4(h4[0], h4[1], h4[2], h4[3]);
    }
    if (t < 64) {
        g_e1s[bx * 64 + t] = (ered[t * 4]     + ered[t * 4 + 2]) * L2E;
        g_e2s[bx * 64 + t] = (ered[t * 4 + 1] + ered[t * 4 + 3]) * L2E;
    }
}

// ---------------------------------------------------------------------------
// Kernel 3 (main): fused masked-exp + fp16 HMMA attention GEMM, 148 CTAs,
// CK=128 chunks. Exactly the proven R14 version (98.8us build).
// ---------------------------------------------------------------------------
__global__ __launch_bounds__(512, 1) void k_main(const int* __restrict__ adj)
{
    extern __shared__ unsigned char smem[];
    const uint32_t sb = smem_u32(smem);
    const int t = threadIdx.x, w = t >> 5, l = t & 31;
    const int bx = blockIdx.x, by = blockIdx.y;
    const int g = l >> 2, qh = l & 3, q2 = qh * 2;
    const int nrg = (bx == 36) ? 8 : 14;
    const bool act = (w < nrg);
    const int rowb = bx * 224 + w * 16;
    const size_t jbase = (size_t)by * JBLK;

    const unsigned char* bt0 = g_bt + (size_t)by * NCH * CHUNK_B;
    #pragma unroll
    for (int c = 0; c < 2; c++) {
        uint32_t dst = sb + c * CHUNK_B + t * 16;
        const unsigned char* src = bt0 + (size_t)c * CHUNK_B + t * 16;
        #pragma unroll
        for (int i = 0; i < 4; i++) CP_ASYNC(dst + i * 8192, src + i * 8192);
        CP_COMMIT();
    }

    float se1g = 0.f, se1h = 0.f;
    const int* pg = adj;
    const int* ph = adj;
    int4 avg = make_int4(0,0,0,0), avh = make_int4(0,0,0,0);
    int joff = 4 * qh;
    if (act) {
        se1g = g_e1s[rowb + g];
        se1h = g_e1s[rowb + g + 8];
        pg = adj + (size_t)(rowb + g) * NN + jbase;
        ph = adj + (size_t)(rowb + g + 8) * NN + jbase;
        avg = __ldg((const int4*)(pg + joff));
        avh = __ldg((const int4*)(ph + joff));
    }

    float c_[16][4];
    #pragma unroll
    for (int td = 0; td < 16; td++)
        #pragma unroll
        for (int k = 0; k < 4; k++) c_[td][k] = 0.f;
    float crs[4] = {0.f, 0.f, 0.f, 0.f};
    const uint32_t bones[2] = {0x3C003C00u, 0x3C003C00u};

    for (int c = 0; c < NCH; c++) {
        CP_WAIT1();
        __syncthreads();
        const uint32_t bufb = sb + (c & 1) * CHUNK_B;

        if (act) {
            #pragma unroll
            for (int s = 0; s < 8; s++) {
                const float4 ev = *(const float4*)(g_e2s + jbase + joff);

                const int4 bg = avg, bh_ = avh;
                if (!(c == NCH - 1 && s == 7)) {
                    joff += 16;
                    avg = __ldg((const int4*)(pg + joff));
                    avh = __ldg((const int4*)(ph + joff));
                }

                float pa0 = pcalc(se1g, ev.x), pa1 = pcalc(se1g, ev.y);
                float pa2 = pcalc(se1g, ev.z), pa3 = pcalc(se1g, ev.w);
                float pb0 = pcalc(se1h, ev.x), pb1 = pcalc(se1h, ev.y);
                float pb2 = pcalc(se1h, ev.z), pb3 = pcalc(se1h, ev.w);

                uint32_t a[4];
                a[0] = packmask(pa0, pa1, bg.x, bg.y);
                a[1] = packmask(pb0, pb1, bh_.x, bh_.y);
                a[2] = packmask(pa2, pa3, bg.z, bg.w);
                a[3] = packmask(pb2, pb3, bh_.z, bh_.w);

                #pragma unroll
                for (int dp = 0; dp < 8; dp++) {
                    uint32_t bh[4];
                    const uint32_t ad = bufb + (s >> 2) * TB64
                                      + ((s & 3) * 8 + dp) * 512
                                      + (l >> 3) * 128 + (l & 7) * 16;
                    LDMX4(bh, ad);
                    mma16816(c_[2 * dp],     a, bh);
                    mma16816(c_[2 * dp + 1], a, bh + 2);
                }
                mma16816(crs, a, bones);
            }
        }

        __syncthreads();
        if (c + 2 < NCH) {
            uint32_t dst = sb + (c & 1) * CHUNK_B + t * 16;
            const unsigned char* src = bt0 + (size_t)(c + 2) * CHUNK_B + t * 16;
            #pragma unroll
            for (int i = 0; i < 4; i++) CP_ASYNC(dst + i * 8192, src + i * 8192);
        }
        CP_COMMIT();
    }

    if (act) {
        if (qh == 0) {
            g_psum[by][rowb + g]     = crs[0];
            g_psum[by][rowb + g + 8] = crs[2];
        }
        float* pb = g_part[by];
        #pragma unroll
        for (int td = 0; td < 16; td++) {
            const int col = td * 8 + q2;
            *(float2*)(pb + (size_t)(rowb + g) * FOUT + col) =
                make_float2(c_[td][0], c_[td][1]);
            *(float2*)(pb + (size_t)(rowb + g + 8) * FOUT + col) =
                make_float2(c_[td][2], c_[td][3]);
        }
    }
}

// ---------------------------------------------------------------------------
// Kernel 4 (final): combine j-split partials, normalize, fast ELU.
// High-MLP version: 4 elements/thread, all 16 part-float4 + 16 psum loads
// issued up-front (independent across u), then compute.
// ---------------------------------------------------------------------------
__global__ __launch_bounds__(256) void k_final(float* __restrict__ out)
{
    const int t0 = blockIdx.x * 256 + threadIdx.x;   // 65536 threads
    float4 a[4][JSPLIT];
    float  ps[4][JSPLIT];
    #pragma unroll
    for (int u = 0; u < 4; u++) {
        const int idx = t0 + u * 65536;
        const int r = idx >> 5;
        #pragma unroll
        for (int p = 0; p < JSPLIT; p++) {
            a[u][p]  = ((const float4*)g_part[p])[idx];
            ps[u][p] = g_psum[p][r];
        }
    }
    #pragma unroll
    for (int u = 0; u < 4; u++) {
        const int idx = t0 + u * 65536;
        float4 v = a[u][0];
        v.x += a[u][1].x + a[u][2].x + a[u][3].x;
        v.y += a[u][1].y + a[u][2].y + a[u][3].y;
        v.z += a[u][1].z + a[u][2].z + a[u][3].z;
        v.w += a[u][1].w + a[u][2].w + a[u][3].w;
        const float inv = 1.f / (ps[u][0] + ps[u][1] + ps[u][2] + ps[u][3]);
        float o[4] = { v.x * inv, v.y * inv, v.z * inv, v.w * inv };
        #pragma unroll
        for (int i = 0; i < 4; i++)
            o[i] = o[i] > 0.f ? o[i] : (ex2f(o[i] * L2E) - 1.f);
        ((float4*)out)[idx] = make_float4(o[0], o[1], o[2], o[3]);
    }
}

// ---------------------------------------------------------------------------
extern "C" void kernel_launch(void* const* d_in, const int* in_sizes, int n_in,
                              void* d_out, int out_size)
{
    const float* x     = (const float*)d_in[0];
    const int*   adj   = (const int*)d_in[1];
    const float* trans = (const float*)d_in[2];
    const float* aw    = (const float*)d_in[3];
    float*       out   = (float*)d_out;

    cudaFuncSetAttribute(k_hgemm, cudaFuncAttributeMaxDynamicSharedMemorySize, 2 * HB);
    cudaFuncSetAttribute(k_main,  cudaFuncAttributeMaxDynamicSharedMemorySize, 2 * CHUNK_B);

    k_cvt<<<528, 256>>>(x, trans);
    k_hgemm<<<128, 256, 2 * HB>>>(aw);
    dim3 gmain(37, JSPLIT);
    k_main<<<gmain, 512, 2 * CHUNK_B>>>(adj);
    k_final<<<256, 256>>>(out);
}